// round 4
// baseline (speedup 1.0000x reference)
#include <cuda_runtime.h>
#include <cstdint>

// Block-diagonal GEMM via mma.sync tf32, full cp.async staging, 3-stage pipeline.
// x:      [16384, 4096] fp32, logical [tokens, 8, 512]   (A fed raw -> HW-truncated tf32)
// blocks: [8, 512, 512] fp32 ([k][n] per block)          (B pre-transposed, bias-compensated, rna-rounded)
// out[m, kb*512+n] = sum_k x[m, kb*512+k] * blocks[kb, k, n]

#define HIDDEN 4096
#define BLKD   512
#define NB     8
#define BM     128
#define BN     128
#define BK     32            // 32 tf32 = 128 B per smem row
#define NITER  (BLKD / BK)   // 16
#define NTH    256
#define STAGES 3

#define ABYTES (BM * BK * 4)             // 16384
#define BBYTES (BN * BK * 4)             // 16384
#define BUFBYTES (ABYTES + BBYTES)       // 32768
#define SMEM_BYTES (STAGES * BUFBYTES)   // 98304

// Transposed + bias-compensated + tf32(rna)-rounded blocks: bt[kb][n][k]
__device__ float g_bt[NB * BLKD * BLKD];

// A is consumed as raw fp32 bits -> HW truncates 13 LSBs (shrinks |A| by ~2^-11*ln2).
// Compensate by scaling B up by the mean truncation factor.
#define TRUNC_COMP 1.000339f

#define SWZ(o) ((o) ^ (((o) >> 3) & 0x70))

static __device__ __forceinline__ uint32_t smem_u32(const void* p) {
    uint32_t a;
    asm("{ .reg .u64 t; cvta.to.shared.u64 t, %1; cvt.u32.u64 %0, t; }"
        : "=r"(a) : "l"(p));
    return a;
}
static __device__ __forceinline__ uint32_t f2tf32(float f) {
    uint32_t r;
    asm("cvt.rna.tf32.f32 %0, %1;" : "=r"(r) : "f"(f));
    return r;
}

#define LDSM4(r0, r1, r2, r3, addr)                                          \
    asm volatile("ldmatrix.sync.aligned.m8n8.x4.shared.b16 {%0,%1,%2,%3}, [%4];" \
                 : "=r"(r0), "=r"(r1), "=r"(r2), "=r"(r3) : "r"(addr))

#define MMA_TF32(c, a, b)                                                    \
    asm volatile("mma.sync.aligned.m16n8k8.row.col.f32.tf32.tf32.f32 "       \
                 "{%0,%1,%2,%3}, {%4,%5,%6,%7}, {%8,%9}, {%0,%1,%2,%3};"     \
                 : "+f"((c)[0]), "+f"((c)[1]), "+f"((c)[2]), "+f"((c)[3])    \
                 : "r"((a)[0]), "r"((a)[1]), "r"((a)[2]), "r"((a)[3]),       \
                   "r"((b)[0]), "r"((b)[1]))

#define CPASYNC16(dst, src)                                                  \
    asm volatile("cp.async.cg.shared.global [%0], [%1], 16;"                 \
                 :: "r"(dst), "l"(src) : "memory")

// ---------------- pre-pass: transpose + compensate + tf32-round blocks ----------------
__global__ void prep_b_kernel(const float* __restrict__ blocks) {
    __shared__ float tile[32][33];
    const int kb = blockIdx.z;
    const int k0 = blockIdx.x * 32, n0 = blockIdx.y * 32;
    const int tx = threadIdx.x, ty = threadIdx.y;  // 32 x 8
    #pragma unroll
    for (int i = 0; i < 32; i += 8)
        tile[ty + i][tx] = blocks[(size_t)kb * BLKD * BLKD + (size_t)(k0 + ty + i) * BLKD + n0 + tx];
    __syncthreads();
    uint32_t* bt = reinterpret_cast<uint32_t*>(g_bt);
    #pragma unroll
    for (int i = 0; i < 32; i += 8)
        bt[(size_t)kb * BLKD * BLKD + (size_t)(n0 + ty + i) * BLKD + k0 + tx] =
            f2tf32(tile[tx][ty + i] * TRUNC_COMP);
}

// ---------------- main GEMM ----------------
__global__ __launch_bounds__(NTH, 2)
void tpt_mma_kernel(const float* __restrict__ x, float* __restrict__ out) {
    extern __shared__ __align__(1024) char smem[];
    const uint32_t sbase = smem_u32(smem);

    const int kb = blockIdx.z;
    const int m0 = blockIdx.x * BM;
    const int n0 = blockIdx.y * BN;
    const int tid = threadIdx.x;
    const int wid = tid >> 5, l = tid & 31;
    const int wm0 = (wid & 1) * 64;   // warp M offset within tile
    const int wn0 = (wid >> 1) * 32;  // warp N offset within tile

    // staging map: thread -> (rows rbase+32i, 16B-chunk q), i = 0..3
    const int q = tid & 7;
    const int rbase = tid >> 3;  // 0..31
    const uint32_t stg_swz = SWZ((uint32_t)(rbase * 128 + q * 16));  // +i*4096 safe

    const float* Ag = x + (size_t)(m0 + rbase) * HIDDEN + kb * BLKD + q * 4;
    const float* Bg = g_bt + (size_t)kb * BLKD * BLKD + (size_t)(n0 + rbase) * BLKD + q * 4;

    float acc[4][4][4];
    #pragma unroll
    for (int mi = 0; mi < 4; mi++)
        #pragma unroll
        for (int nt = 0; nt < 4; nt++)
            #pragma unroll
            for (int r = 0; r < 4; r++) acc[mi][nt][r] = 0.0f;

    // ldmatrix per-lane address components
    const int mat = l >> 3;          // 0..3
    const int r8  = l & 7;
    const int a_rowadd = (mat & 1) * 8 + r8;   // A: m8 pair stacked in M, then K
    const int a_colb   = (mat >> 1) * 16;
    const int b_rowadd = (mat >> 1) * 8 + r8;  // B: k-halves first, then N
    const int b_colb   = (mat & 1) * 16;

    // issue cp.async for chunk kt into stage buffer
    auto issue_stage = [&](int kt) {
        const uint32_t buf = sbase + (uint32_t)(kt % STAGES) * BUFBYTES;
        const float* asrc = Ag + (size_t)kt * BK;
        const float* bsrc = Bg + (size_t)kt * BK;
        #pragma unroll
        for (int i = 0; i < 4; i++)
            CPASYNC16(buf + stg_swz + i * 4096u, asrc + (size_t)i * 32 * HIDDEN);
        #pragma unroll
        for (int i = 0; i < 4; i++)
            CPASYNC16(buf + ABYTES + stg_swz + i * 4096u, bsrc + (size_t)i * 32 * BLKD);
        asm volatile("cp.async.commit_group;" ::: "memory");
    };

    // prologue: stages 0 and 1 in flight
    issue_stage(0);
    issue_stage(1);

    #pragma unroll 1
    for (int kt = 0; kt < NITER; kt++) {
        if (kt + 1 < NITER) {
            asm volatile("cp.async.wait_group 1;" ::: "memory");
        } else {
            asm volatile("cp.async.wait_group 0;" ::: "memory");
        }
        __syncthreads();

        // prefetch stage kt+2 (buffer was consumed at iter kt-1; barrier above protects it)
        if (kt + 2 < NITER) issue_stage(kt + 2);

        // ---- compute on stage kt%STAGES: 4 k8-steps ----
        const uint32_t abase = sbase + (uint32_t)(kt % STAGES) * BUFBYTES;
        const uint32_t bbase = abase + ABYTES;
        #pragma unroll
        for (int ks = 0; ks < 4; ks++) {
            uint32_t aF[4][4], bF[4][2];
            #pragma unroll
            for (int mi = 0; mi < 4; mi++) {
                uint32_t off = (uint32_t)((wm0 + mi * 16 + a_rowadd) * 128 + a_colb + ks * 32);
                LDSM4(aF[mi][0], aF[mi][1], aF[mi][2], aF[mi][3], abase + SWZ(off));
            }
            #pragma unroll
            for (int p = 0; p < 2; p++) {
                uint32_t off = (uint32_t)((wn0 + p * 16 + b_rowadd) * 128 + b_colb + ks * 32);
                LDSM4(bF[2 * p][0], bF[2 * p][1], bF[2 * p + 1][0], bF[2 * p + 1][1],
                      bbase + SWZ(off));
            }
            #pragma unroll
            for (int mi = 0; mi < 4; mi++)
                #pragma unroll
                for (int nt = 0; nt < 4; nt++)
                    MMA_TF32(acc[mi][nt], aF[mi], bF[nt]);
        }
        __syncthreads();  // compute done before next iter's prefetch reuses this buffer
    }

    // ---- epilogue: direct float2 stores ----
    #pragma unroll
    for (int mi = 0; mi < 4; mi++) {
        const int grow = m0 + wm0 + mi * 16 + (l >> 2);
        #pragma unroll
        for (int nt = 0; nt < 4; nt++) {
            const int gcol = kb * BLKD + n0 + wn0 + nt * 8 + 2 * (l & 3);
            float2 v01 = make_float2(acc[mi][nt][0], acc[mi][nt][1]);
            float2 v23 = make_float2(acc[mi][nt][2], acc[mi][nt][3]);
            *reinterpret_cast<float2*>(out + (size_t)grow * HIDDEN + gcol) = v01;
            *reinterpret_cast<float2*>(out + (size_t)(grow + 8) * HIDDEN + gcol) = v23;
        }
    }
}

extern "C" void kernel_launch(void* const* d_in, const int* in_sizes, int n_in,
                              void* d_out, int out_size) {
    const float* x      = (const float*)d_in[0];
    const float* blocks = (const float*)d_in[1];
    float*       out    = (float*)d_out;

    const int M = in_sizes[0] / HIDDEN;  // 16384

    cudaFuncSetAttribute(tpt_mma_kernel,
                         cudaFuncAttributeMaxDynamicSharedMemorySize, SMEM_BYTES);

    dim3 gp(BLKD / 32, BLKD / 32, NB), bp(32, 8);
    prep_b_kernel<<<gp, bp>>>(blocks);

    dim3 gg(M / BM, BLKD / BN, NB), bg(NTH);
    tpt_mma_kernel<<<gg, bg, SMEM_BYTES>>>(x, out);
}

// round 5
// speedup vs baseline: 2.0680x; 2.0680x over previous
#include <cuda_runtime.h>
#include <cuda_fp16.h>
#include <cstdint>

// Block-diagonal GEMM via mma.sync fp16 (f32 accumulate), cp.async 3-stage pipeline.
// x:      [16384, 4096] fp32 -> pre-converted to fp16 scratch g_xh
// blocks: [8, 512, 512] fp32 [k][n] -> pre-transposed fp16 [n][k] scratch g_bt16
// out[m, kb*512+n] = sum_k x[m, kb*512+k] * blocks[kb, k, n]

#define HIDDEN 4096
#define BLKD   512
#define NB     8
#define BM     128
#define BN     128
#define BK     64            // 64 halves = 128 B per smem row
#define NITER  (BLKD / BK)   // 8
#define NTH    256
#define STAGES 3

#define ABYTES (BM * BK * 2)             // 16384
#define BBYTES (BN * BK * 2)             // 16384
#define BUFBYTES (ABYTES + BBYTES)       // 32768
#define SMEM_BYTES (STAGES * BUFBYTES)   // 98304

// fp16 scratch (static device allocations — allowed)
__device__ __half g_xh[16384 * HIDDEN];          // 134 MB
__device__ __half g_bt16[NB * BLKD * BLKD];      // 4 MB, layout [kb][n][k]

#define SWZ(o) ((o) ^ (((o) >> 3) & 0x70))

static __device__ __forceinline__ uint32_t smem_u32(const void* p) {
    uint32_t a;
    asm("{ .reg .u64 t; cvta.to.shared.u64 t, %1; cvt.u32.u64 %0, t; }"
        : "=r"(a) : "l"(p));
    return a;
}

#define LDSM4(r0, r1, r2, r3, addr)                                          \
    asm volatile("ldmatrix.sync.aligned.m8n8.x4.shared.b16 {%0,%1,%2,%3}, [%4];" \
                 : "=r"(r0), "=r"(r1), "=r"(r2), "=r"(r3) : "r"(addr))

#define MMA_F16(c, a, b)                                                     \
    asm volatile("mma.sync.aligned.m16n8k16.row.col.f32.f16.f16.f32 "        \
                 "{%0,%1,%2,%3}, {%4,%5,%6,%7}, {%8,%9}, {%0,%1,%2,%3};"     \
                 : "+f"((c)[0]), "+f"((c)[1]), "+f"((c)[2]), "+f"((c)[3])    \
                 : "r"((a)[0]), "r"((a)[1]), "r"((a)[2]), "r"((a)[3]),       \
                   "r"((b)[0]), "r"((b)[1]))

#define CPASYNC16(dst, src)                                                  \
    asm volatile("cp.async.cg.shared.global [%0], [%1], 16;"                 \
                 :: "r"(dst), "l"(src) : "memory")

// ---------------- pre-pass 1: x fp32 -> fp16 ----------------
__global__ __launch_bounds__(256)
void prep_a_kernel(const float* __restrict__ x, long long n8) {
    long long i = (long long)blockIdx.x * 256 + threadIdx.x;  // one i = 8 elements
    if (i >= n8) return;
    const float4* src = reinterpret_cast<const float4*>(x) + 2 * i;
    float4 v0 = src[0], v1 = src[1];
    __half2 h0 = __floats2half2_rn(v0.x, v0.y);
    __half2 h1 = __floats2half2_rn(v0.z, v0.w);
    __half2 h2 = __floats2half2_rn(v1.x, v1.y);
    __half2 h3 = __floats2half2_rn(v1.z, v1.w);
    uint4 o;
    o.x = *reinterpret_cast<uint32_t*>(&h0);
    o.y = *reinterpret_cast<uint32_t*>(&h1);
    o.z = *reinterpret_cast<uint32_t*>(&h2);
    o.w = *reinterpret_cast<uint32_t*>(&h3);
    reinterpret_cast<uint4*>(g_xh)[i] = o;
}

// ---------------- pre-pass 2: transpose + fp16 blocks -> [n][k] ----------------
__global__ void prep_b_kernel(const float* __restrict__ blocks) {
    __shared__ float tile[32][33];
    const int kb = blockIdx.z;
    const int k0 = blockIdx.x * 32, n0 = blockIdx.y * 32;
    const int tx = threadIdx.x, ty = threadIdx.y;  // 32 x 8
    #pragma unroll
    for (int i = 0; i < 32; i += 8)
        tile[ty + i][tx] = blocks[(size_t)kb * BLKD * BLKD + (size_t)(k0 + ty + i) * BLKD + n0 + tx];
    __syncthreads();
    #pragma unroll
    for (int i = 0; i < 32; i += 8)
        g_bt16[(size_t)kb * BLKD * BLKD + (size_t)(n0 + ty + i) * BLKD + k0 + tx] =
            __float2half_rn(tile[tx][ty + i]);
}

// ---------------- main GEMM ----------------
__global__ __launch_bounds__(NTH, 2)
void tpt_mma16_kernel(float* __restrict__ out) {
    extern __shared__ __align__(1024) char smem[];
    const uint32_t sbase = smem_u32(smem);

    const int kb = blockIdx.z;
    const int m0 = blockIdx.x * BM;
    const int n0 = blockIdx.y * BN;
    const int tid = threadIdx.x;
    const int wid = tid >> 5, l = tid & 31;
    const int wm0 = (wid & 1) * 64;   // warp M offset
    const int wn0 = (wid >> 1) * 32;  // warp N offset

    // staging map: thread -> (rows rbase+32i, 16B-chunk q), i = 0..3
    const int q = tid & 7;
    const int rbase = tid >> 3;  // 0..31
    const uint32_t stg_swz = SWZ((uint32_t)(rbase * 128 + q * 16));  // +i*4096 safe

    const __half* Ag = g_xh + (size_t)(m0 + rbase) * HIDDEN + kb * BLKD + q * 8;
    const __half* Bg = g_bt16 + (size_t)kb * BLKD * BLKD + (size_t)(n0 + rbase) * BLKD + q * 8;

    float acc[4][4][4];
    #pragma unroll
    for (int mi = 0; mi < 4; mi++)
        #pragma unroll
        for (int nt = 0; nt < 4; nt++)
            #pragma unroll
            for (int r = 0; r < 4; r++) acc[mi][nt][r] = 0.0f;

    // ldmatrix per-lane address components (b16, 8x8 tile = 16B rows)
    const int mat = l >> 3;          // 0..3
    const int r8  = l & 7;
    const int a_rowadd = (mat & 1) * 8 + r8;   // A mats: (m0,k0),(m8,k0),(m0,k8),(m8,k8)
    const int a_colb   = (mat >> 1) * 16;
    const int b_rowadd = (mat >> 1) * 8 + r8;  // B mats: (n0,k0),(n0,k8),(n8,k0),(n8,k8)
    const int b_colb   = (mat & 1) * 16;

    auto issue_stage = [&](int kt) {
        const uint32_t buf = sbase + (uint32_t)(kt % STAGES) * BUFBYTES;
        const __half* asrc = Ag + (size_t)kt * BK;
        const __half* bsrc = Bg + (size_t)kt * BK;
        #pragma unroll
        for (int i = 0; i < 4; i++)
            CPASYNC16(buf + stg_swz + i * 4096u, asrc + (size_t)i * 32 * HIDDEN);
        #pragma unroll
        for (int i = 0; i < 4; i++)
            CPASYNC16(buf + ABYTES + stg_swz + i * 4096u, bsrc + (size_t)i * 32 * BLKD);
        asm volatile("cp.async.commit_group;" ::: "memory");
    };

    issue_stage(0);
    issue_stage(1);

    #pragma unroll 1
    for (int kt = 0; kt < NITER; kt++) {
        if (kt + 1 < NITER) {
            asm volatile("cp.async.wait_group 1;" ::: "memory");
        } else {
            asm volatile("cp.async.wait_group 0;" ::: "memory");
        }
        __syncthreads();  // single barrier per iter: also protects buffer reuse below

        if (kt + 2 < NITER) issue_stage(kt + 2);

        const uint32_t abase = sbase + (uint32_t)(kt % STAGES) * BUFBYTES;
        const uint32_t bbase = abase + ABYTES;
        #pragma unroll
        for (int ks = 0; ks < 4; ks++) {          // 4 x k16 steps (BK=64)
            uint32_t aF[4][4], bF[4][2];
            #pragma unroll
            for (int mi = 0; mi < 4; mi++) {
                uint32_t off = (uint32_t)((wm0 + mi * 16 + a_rowadd) * 128 + a_colb + ks * 32);
                LDSM4(aF[mi][0], aF[mi][1], aF[mi][2], aF[mi][3], abase + SWZ(off));
            }
            #pragma unroll
            for (int p = 0; p < 2; p++) {
                uint32_t off = (uint32_t)((wn0 + p * 16 + b_rowadd) * 128 + b_colb + ks * 32);
                LDSM4(bF[2 * p][0], bF[2 * p][1], bF[2 * p + 1][0], bF[2 * p + 1][1],
                      bbase + SWZ(off));
            }
            #pragma unroll
            for (int mi = 0; mi < 4; mi++)
                #pragma unroll
                for (int nt = 0; nt < 4; nt++)
                    MMA_F16(acc[mi][nt], aF[mi], bF[nt]);
        }
    }

    // ---- epilogue: direct float2 stores ----
    #pragma unroll
    for (int mi = 0; mi < 4; mi++) {
        const int grow = m0 + wm0 + mi * 16 + (l >> 2);
        #pragma unroll
        for (int nt = 0; nt < 4; nt++) {
            const int gcol = kb * BLKD + n0 + wn0 + nt * 8 + 2 * (l & 3);
            float2 v01 = make_float2(acc[mi][nt][0], acc[mi][nt][1]);
            float2 v23 = make_float2(acc[mi][nt][2], acc[mi][nt][3]);
            *reinterpret_cast<float2*>(out + (size_t)grow * HIDDEN + gcol) = v01;
            *reinterpret_cast<float2*>(out + (size_t)(grow + 8) * HIDDEN + gcol) = v23;
        }
    }
}

extern "C" void kernel_launch(void* const* d_in, const int* in_sizes, int n_in,
                              void* d_out, int out_size) {
    const float* x      = (const float*)d_in[0];
    const float* blocks = (const float*)d_in[1];
    float*       out    = (float*)d_out;

    const int M = in_sizes[0] / HIDDEN;  // 16384
    const long long n8 = (long long)M * HIDDEN / 8;

    cudaFuncSetAttribute(tpt_mma16_kernel,
                         cudaFuncAttributeMaxDynamicSharedMemorySize, SMEM_BYTES);

    prep_a_kernel<<<(unsigned)((n8 + 255) / 256), 256>>>(x, n8);

    dim3 gp(BLKD / 32, BLKD / 32, NB), bp(32, 8);
    prep_b_kernel<<<gp, bp>>>(blocks);

    dim3 gg(M / BM, BLKD / BN, NB), bg(NTH);
    tpt_mma16_kernel<<<gg, bg, SMEM_BYTES>>>(out);
}